// round 1
// baseline (speedup 1.0000x reference)
#include <cuda_runtime.h>

#define NF    22528          // NUM_FEATURES
#define NOUT  520            // HIDDEN + BUCKET_NB
#define HID   512
#define NROWS 8192
#define MAXIDX 512
#define SCALE_O 400.0f

// Transposed feature-transform weights: W_ftT[f][o] = W_ft[o][f]. 46.9 MB scratch.
__device__ float g_WftT[(size_t)NF * NOUT];

// ---------------------------------------------------------------------------
// Kernel 0: transpose W_ft [520, 22528] -> g_WftT [22528, 520]
// ---------------------------------------------------------------------------
__global__ void transpose_wft(const float* __restrict__ W) {
    __shared__ float tile[32][33];
    int f0 = blockIdx.x * 32;
    int o0 = blockIdx.y * 32;
    int tx = threadIdx.x;   // 0..31
    int ty = threadIdx.y;   // 0..7
#pragma unroll
    for (int i = 0; i < 4; i++) {
        int o = o0 + ty + 8 * i;
        float v = 0.0f;
        if (o < NOUT) v = W[(size_t)o * NF + f0 + tx];     // coalesced in f
        tile[ty + 8 * i][tx] = v;
    }
    __syncthreads();
#pragma unroll
    for (int i = 0; i < 4; i++) {
        int f = f0 + ty + 8 * i;
        int o = o0 + tx;
        if (o < NOUT)
            g_WftT[(size_t)f * NOUT + o] = tile[tx][ty + 8 * i];  // coalesced in o
    }
}

// ---------------------------------------------------------------------------
// Kernel 1: one block per batch row. Sparse feature transform + per-bucket MLP.
// ---------------------------------------------------------------------------
__device__ __forceinline__ float clip01(float v) {
    return fminf(fmaxf(v, 0.0f), 1.0f);
}

__global__ __launch_bounds__(256, 8) void nnue_row(
    const float* __restrict__ wf,      // [8192, 22528]
    const float* __restrict__ bfeat,   // [8192, 22528]
    const float* __restrict__ stm_arr, // [8192, 1]
    const int*   __restrict__ buckets, // [8192]
    const float* __restrict__ b_ft,    // [520]
    const float* __restrict__ W1,      // [8, 32, 1024]
    const float* __restrict__ b1,      // [8, 32]
    const float* __restrict__ W2,      // [8, 32, 32]
    const float* __restrict__ b2,      // [8, 32]
    const float* __restrict__ W3,      // [8, 1, 32]
    const float* __restrict__ b3,      // [8, 1]
    float*       __restrict__ out)     // [8192]
{
    __shared__ int   s_idxW[MAXIDX];
    __shared__ int   s_idxB[MAXIDX];
    __shared__ int   s_cntW, s_cntB;
    __shared__ float s_accW[NOUT];
    __shared__ float s_accB[NOUT];
    __shared__ float s_x[1024];
    __shared__ float s_h1[32];

    const int row = blockIdx.x;
    const int tid = threadIdx.x;

    if (tid == 0) { s_cntW = 0; s_cntB = 0; }
    __syncthreads();

    // ---- Phase A: stream-scan the two feature rows, collect active indices ----
    {
        const float4* w4 = (const float4*)(wf    + (size_t)row * NF);
        const float4* b4 = (const float4*)(bfeat + (size_t)row * NF);
        for (int u = tid; u < NF / 4; u += 256) {
            float4 v = __ldcs(&w4[u]);           // streaming: don't pollute L2
            if (v.x != 0.0f) { int p = atomicAdd(&s_cntW, 1); if (p < MAXIDX) s_idxW[p] = 4 * u + 0; }
            if (v.y != 0.0f) { int p = atomicAdd(&s_cntW, 1); if (p < MAXIDX) s_idxW[p] = 4 * u + 1; }
            if (v.z != 0.0f) { int p = atomicAdd(&s_cntW, 1); if (p < MAXIDX) s_idxW[p] = 4 * u + 2; }
            if (v.w != 0.0f) { int p = atomicAdd(&s_cntW, 1); if (p < MAXIDX) s_idxW[p] = 4 * u + 3; }
            float4 q = __ldcs(&b4[u]);
            if (q.x != 0.0f) { int p = atomicAdd(&s_cntB, 1); if (p < MAXIDX) s_idxB[p] = 4 * u + 0; }
            if (q.y != 0.0f) { int p = atomicAdd(&s_cntB, 1); if (p < MAXIDX) s_idxB[p] = 4 * u + 1; }
            if (q.z != 0.0f) { int p = atomicAdd(&s_cntB, 1); if (p < MAXIDX) s_idxB[p] = 4 * u + 2; }
            if (q.w != 0.0f) { int p = atomicAdd(&s_cntB, 1); if (p < MAXIDX) s_idxB[p] = 4 * u + 3; }
        }
    }
    __syncthreads();
    const int cw = min(s_cntW, MAXIDX);
    const int cb = min(s_cntB, MAXIDX);

    // ---- Phase B: register accumulators, gather rows of W_ftT (L2-resident) ----
    // thread t owns cols {t, t+256}; threads 0..7 also own {512+t}
    float aw0 = __ldg(&b_ft[tid]);
    float aw1 = __ldg(&b_ft[tid + 256]);
    float aw2 = (tid < 8) ? __ldg(&b_ft[512 + tid]) : 0.0f;
    float ab0 = aw0, ab1 = aw1, ab2 = aw2;

#pragma unroll 4
    for (int i = 0; i < cw; i++) {
        const float* r = g_WftT + (size_t)s_idxW[i] * NOUT;
        aw0 += r[tid];
        aw1 += r[tid + 256];
        if (tid < 8) aw2 += r[512 + tid];
    }
#pragma unroll 4
    for (int i = 0; i < cb; i++) {
        const float* r = g_WftT + (size_t)s_idxB[i] * NOUT;
        ab0 += r[tid];
        ab1 += r[tid + 256];
        if (tid < 8) ab2 += r[512 + tid];
    }

    s_accW[tid] = aw0;       s_accW[tid + 256] = aw1;
    s_accB[tid] = ab0;       s_accB[tid + 256] = ab1;
    if (tid < 8) { s_accW[512 + tid] = aw2; s_accB[512 + tid] = ab2; }
    __syncthreads();

    // ---- Phase C: stm-ordered clip into x[1024], then per-bucket MLP ----
    const float stm = stm_arr[row];           // exactly 0.0 or 1.0
    const int   k   = buckets[row];
    const float* first  = (stm == 0.0f) ? s_accW : s_accB;
    const float* second = (stm == 0.0f) ? s_accB : s_accW;

    s_x[tid]       = clip01(first[tid]);
    s_x[tid + 256] = clip01(first[tid + 256]);
    s_x[tid + 512] = clip01(second[tid]);
    s_x[tid + 768] = clip01(second[tid + 256]);
    __syncthreads();

    // Layer 1: 32 outputs; warp w computes outputs 4w..4w+3
    const int warp = tid >> 5, lane = tid & 31;
    const float* W1k = W1 + (size_t)k * 32 * 1024;
#pragma unroll
    for (int oo = 0; oo < 4; oo++) {
        const int o = warp * 4 + oo;
        const float* wr = W1k + o * 1024;
        float s = 0.0f;
#pragma unroll
        for (int j = 0; j < 32; j++)
            s += s_x[lane + 32 * j] * __ldg(&wr[lane + 32 * j]);
#pragma unroll
        for (int d = 16; d; d >>= 1) s += __shfl_xor_sync(0xFFFFFFFFu, s, d);
        if (lane == 0) s_h1[o] = clip01(s + __ldg(&b1[k * 32 + o]));
    }
    __syncthreads();

    // Layers 2+3 + psqt + output: warp 0 only
    if (warp == 0) {
        const float* W2k = W2 + k * 32 * 32;
        float s = 0.0f;
#pragma unroll
        for (int i = 0; i < 32; i++)
            s += s_h1[i] * __ldg(&W2k[lane * 32 + i]);
        float h2 = clip01(s + __ldg(&b2[k * 32 + lane]));

        float p = h2 * __ldg(&W3[k * 32 + lane]);
#pragma unroll
        for (int d = 16; d; d >>= 1) p += __shfl_xor_sync(0xFFFFFFFFu, p, d);

        if (lane == 0) {
            float o3   = p + __ldg(&b3[k]);
            float psqt = (s_accW[512 + k] - s_accB[512 + k]) * (0.5f - stm);
            out[row] = (o3 + psqt) * SCALE_O;
        }
    }
}

// ---------------------------------------------------------------------------
// Harness entry
// ---------------------------------------------------------------------------
extern "C" void kernel_launch(void* const* d_in, const int* in_sizes, int n_in,
                              void* d_out, int out_size) {
    const float* wf    = (const float*)d_in[0];   // white_features
    const float* bfeat = (const float*)d_in[1];   // black_features
    const float* stm   = (const float*)d_in[2];   // side_to_move
    const int*   bkt   = (const int*)  d_in[3];   // buckets
    const float* W_ft  = (const float*)d_in[4];
    const float* b_ft  = (const float*)d_in[5];
    const float* W1    = (const float*)d_in[6];
    const float* b1    = (const float*)d_in[7];
    const float* W2    = (const float*)d_in[8];
    const float* b2    = (const float*)d_in[9];
    const float* W3    = (const float*)d_in[10];
    const float* b3    = (const float*)d_in[11];
    float* out = (float*)d_out;

    dim3 tg(NF / 32, (NOUT + 31) / 32);
    transpose_wft<<<tg, dim3(32, 8)>>>(W_ft);
    nnue_row<<<NROWS, 256>>>(wf, bfeat, stm, bkt, b_ft,
                             W1, b1, W2, b2, W3, b3, out);
}